// round 10
// baseline (speedup 1.0000x reference)
#include <cuda_runtime.h>
#include <math.h>

#define NN 256
#define BATCH 4096
#define TROWS 520          // padded step rows (active t: 0..508)

// Scratch (no device allocations allowed)
// SoA layout: g_coef2[t*128 + k*32 + lane] = coef for slot m = 4*lane + k
// (MZI at p = 2m + (t&1)); identity if inactive. Lane stride 16B -> nL=4.
__device__ float4 g_coef2[TROWS * 128];
// Boundary coef for odd steps: g_coefB[t*32 + lane] = coef of slot 4*lane - 1
// (identity for lane 0). Avoids 3 shfls per odd step.
__device__ float4 g_coefB[TROWS * 32];
__device__ float  g_Wt[NN * NN];         // g_Wt[j*NN + i] = Re(e^{i phe_i} U[i][j])

// ---------------------------------------------------------------------------
// Kernel A: schedule-ordered coefficients, SoA + boundary plane.
// ---------------------------------------------------------------------------
__global__ void coef2_kernel(const float* __restrict__ theta,
                             const float* __restrict__ phi) {
    const int t = blockIdx.x;        // 0..TROWS-1
    const int m = threadIdx.x;       // 0..127 (slot)
    const int p = 2 * m + (t & 1);
    const int pmaxs = min(t, 508 - t);   // negative for t > 508
    float4 out = make_float4(1.f, 0.f, 0.f, 0.f);
    if (p <= pmaxs) {                // implies t <= 508, p <= 254, l in range
        const int l = (t - p) >> 1;
        const int idx = l * 255 - ((l * (l - 1)) >> 1) + p;
        float s, c;  sincosf(theta[idx], &s, &c);
        float ei, er; sincosf(phi[idx], &ei, &er);
        out = make_float4(c, s * er, s * ei, 0.f);
    }
    g_coef2[t * 128 + (m & 3) * 32 + (m >> 2)] = out;
    // boundary plane: slot m = 4i-1 feeds lane i's lower boundary
    if ((m & 3) == 3 && m < 127)
        g_coefB[t * 32 + ((m + 1) >> 2)] = out;
    if (m == 0)
        g_coefB[t * 32] = make_float4(1.f, 0.f, 0.f, 0.f);
}

// ---------------------------------------------------------------------------
// Kernel B: one warp per column; rows 8i..8i+7 in lane i's registers.
// Even step: 4 internal MZIs. Odd step: 3 internal + two boundary halves
// (values via 4 shfls; boundary coef preloaded from g_coefB). Identity
// padding keeps the loop branch-free. 6-row register prefetch ring.
// 256 thr/CTA, 8 warps -> 2 warps/SMSP: with SoA coefs the L1tex queue is
// no longer binding, so the co-warp hides shfl/FMA latency.
// ---------------------------------------------------------------------------
#define MZI(cf, x0, y0, x1, y1) do {                       \
    const float c_ = (cf).x, sr_ = (cf).y, si_ = (cf).z;   \
    const float nx0 = c_*(x0) - sr_*(x1) - si_*(y1);       \
    const float ny0 = c_*(y0) - sr_*(y1) + si_*(x1);       \
    const float nx1 = sr_*(x0) - si_*(y0) + c_*(x1);       \
    const float ny1 = sr_*(y0) + si_*(x0) + c_*(y1);       \
    (x0) = nx0; (y0) = ny0; (x1) = nx1; (y1) = ny1;        \
} while (0)

#define LOADP(dst, tt) do {                                            \
    const float4* p_ = &g_coef2[(tt) * 128 + lane];                    \
    dst[0] = __ldg(p_);       dst[1] = __ldg(p_ + 32);                 \
    dst[2] = __ldg(p_ + 64);  dst[3] = __ldg(p_ + 96);                 \
} while (0)

#define LOADB(bdst, tt) do {                                           \
    bdst = __ldg(&g_coefB[(tt) * 32 + lane]);                          \
} while (0)

#define STEP_EVEN(cf) do {                                             \
    MZI(cf[0], vr[0], vi[0], vr[1], vi[1]);                            \
    MZI(cf[1], vr[2], vi[2], vr[3], vi[3]);                            \
    MZI(cf[2], vr[4], vi[4], vr[5], vi[5]);                            \
    MZI(cf[3], vr[6], vi[6], vr[7], vi[7]);                            \
} while (0)

#define STEP_ODD(cf, bcf) do {                                         \
    /* shfls first: vr/vi[0] and [7] untouched by interior MZIs */     \
    const float rx = __shfl_down_sync(0xffffffffu, vr[0], 1);          \
    const float ry = __shfl_down_sync(0xffffffffu, vi[0], 1);          \
    const float lx = __shfl_up_sync(0xffffffffu, vr[7], 1);            \
    const float ly = __shfl_up_sync(0xffffffffu, vi[7], 1);            \
    MZI(cf[0], vr[1], vi[1], vr[2], vi[2]);                            \
    MZI(cf[1], vr[3], vi[3], vr[4], vi[4]);                            \
    MZI(cf[2], vr[5], vi[5], vr[6], vi[6]);                            \
    {   /* upper boundary: this lane's row 7 is v0 -> n0 */            \
        const float c_ = cf[3].x, sr_ = cf[3].y, si_ = cf[3].z;        \
        const float nx = c_*vr[7] - sr_*rx - si_*ry;                   \
        const float ny = c_*vi[7] - sr_*ry + si_*rx;                   \
        vr[7] = nx; vi[7] = ny;                                        \
    }                                                                  \
    {   /* lower boundary: this lane's row 0 is v1 -> n1 */            \
        const float bc = bcf.x, bs = bcf.y, bt = bcf.z;                \
        const float nx = bs*lx - bt*ly + bc*vr[0];                     \
        const float ny = bs*ly + bt*lx + bc*vi[0];                     \
        vr[0] = nx; vi[0] = ny;                                        \
    }                                                                  \
} while (0)

__global__ __launch_bounds__(256, 1) void build_u_kernel(const float* __restrict__ phi_ext) {
    const int lane = threadIdx.x & 31;
    const int j = blockIdx.x * 8 + (threadIdx.x >> 5);   // column, one per warp

    float vr[8], vi[8];
    #pragma unroll
    for (int k = 0; k < 8; ++k) {
        vr[k] = (8 * lane + k == j) ? 1.f : 0.f;
        vi[k] = 0.f;
    }

    float4 e0[4], o0[4], e1[4], o1[4], e2[4], o2[4];
    float4 b0, b1, b2;
    LOADP(e0, 0); LOADP(o0, 1); LOADB(b0, 1);
    LOADP(e1, 2); LOADP(o1, 3); LOADB(b1, 3);
    LOADP(e2, 4); LOADP(o2, 5); LOADB(b2, 5);

    int t = 6;
    #pragma unroll 1
    for (int it = 0; it < 85; ++it) {     // 85*6 = 510 steps (0..509; 509 inert)
        STEP_EVEN(e0); STEP_ODD(o0, b0);
        LOADP(e0, t); LOADP(o0, t + 1); LOADB(b0, t + 1);
        STEP_EVEN(e1); STEP_ODD(o1, b1);
        LOADP(e1, t + 2); LOADP(o1, t + 3); LOADB(b1, t + 3);
        STEP_EVEN(e2); STEP_ODD(o2, b2);
        LOADP(e2, t + 4); LOADP(o2, t + 5); LOADB(b2, t + 5);
        t += 6;
    }

    // phase screen, real part, store column j (transposed W)
    #pragma unroll
    for (int k = 0; k < 8; ++k) {
        const int r = 8 * lane + k;
        float sp, cp;
        sincosf(__ldg(&phi_ext[r]), &sp, &cp);
        g_Wt[j * NN + r] = cp * vr[k] - sp * vi[k];
    }
}

// ---------------------------------------------------------------------------
// Kernel C: out[b,i] = sum_j x[b,j] * Wt[j,i]
// BM=128, BN=64, BK=16, 256 threads, 8x4 per thread, float4 smem paths.
// ---------------------------------------------------------------------------
#define BM 128
#define BN 64
#define BK 16

__global__ __launch_bounds__(256, 2) void gemm_kernel(const float* __restrict__ A,
                                                      float* __restrict__ C) {
    __shared__ float As[BK][BM + 4];
    __shared__ float Ws[BK][BN + 4];

    const int tid = threadIdx.x;
    const int tx = tid & 15;          // n sub-tile (4 cols each)
    const int ty = tid >> 4;          // m sub-tile (8 rows each)
    const int bm0 = blockIdx.x * BM;
    const int bn0 = blockIdx.y * BN;

    // A loading: 256 thr * 8 floats = 2048 = 128x16
    const int lr = tid >> 1;          // 0..127 row
    const int lc = (tid & 1) * 8;     // 0 or 8 (two float4)
    // W loading: 256 thr * 4 floats = 1024 = 16x64
    const int wr = tid >> 4;          // 0..15 k row
    const int wc = (tid & 15) * 4;    // i offset

    float acc[8][4] = {};

    for (int k0 = 0; k0 < NN; k0 += BK) {
        const float4 a4 = *reinterpret_cast<const float4*>(A + (bm0 + lr) * NN + k0 + lc);
        const float4 a5 = *reinterpret_cast<const float4*>(A + (bm0 + lr) * NN + k0 + lc + 4);
        As[lc + 0][lr] = a4.x; As[lc + 1][lr] = a4.y;
        As[lc + 2][lr] = a4.z; As[lc + 3][lr] = a4.w;
        As[lc + 4][lr] = a5.x; As[lc + 5][lr] = a5.y;
        As[lc + 6][lr] = a5.z; As[lc + 7][lr] = a5.w;
        const float4 w4 = *reinterpret_cast<const float4*>(g_Wt + (k0 + wr) * NN + bn0 + wc);
        *reinterpret_cast<float4*>(&Ws[wr][wc]) = w4;
        __syncthreads();

        #pragma unroll
        for (int k = 0; k < BK; ++k) {
            const float4 am0 = *reinterpret_cast<const float4*>(&As[k][ty * 8]);
            const float4 am1 = *reinterpret_cast<const float4*>(&As[k][ty * 8 + 4]);
            const float4 bn  = *reinterpret_cast<const float4*>(&Ws[k][tx * 4]);
            const float a[8] = {am0.x, am0.y, am0.z, am0.w, am1.x, am1.y, am1.z, am1.w};
            const float b[4] = {bn.x, bn.y, bn.z, bn.w};
            #pragma unroll
            for (int i = 0; i < 8; ++i)
                #pragma unroll
                for (int jj = 0; jj < 4; ++jj)
                    acc[i][jj] = fmaf(a[i], b[jj], acc[i][jj]);
        }
        __syncthreads();
    }

    #pragma unroll
    for (int i = 0; i < 8; ++i) {
        float4 r = make_float4(acc[i][0], acc[i][1], acc[i][2], acc[i][3]);
        *reinterpret_cast<float4*>(C + (bm0 + ty * 8 + i) * NN + bn0 + tx * 4) = r;
    }
}

// ---------------------------------------------------------------------------
// Launch: inputs (metadata order): x, theta, phi_internal, phi_external
// ---------------------------------------------------------------------------
extern "C" void kernel_launch(void* const* d_in, const int* in_sizes, int n_in,
                              void* d_out, int out_size) {
    const float* x       = (const float*)d_in[0];
    const float* theta   = (const float*)d_in[1];
    const float* phi_int = (const float*)d_in[2];
    const float* phi_ext = (const float*)d_in[3];
    float* out = (float*)d_out;

    coef2_kernel<<<TROWS, 128>>>(theta, phi_int);
    build_u_kernel<<<NN / 8, 256>>>(phi_ext);
    gemm_kernel<<<dim3(BATCH / BM, NN / BN), 256>>>(x, out);
}

// round 11
// speedup vs baseline: 1.1522x; 1.1522x over previous
#include <cuda_runtime.h>
#include <math.h>

#define NN 256
#define BATCH 4096
#define TROWS 520          // padded step rows (active t: 0..508)

// Scratch (no device allocations allowed)
// SoA layout: g_coef2[t*128 + k*32 + lane] = coef for slot m = 4*lane + k
// (MZI at p = 2m + (t&1)); identity if inactive. Lane stride 16B -> nL=4.
__device__ float4 g_coef2[TROWS * 128];
// Boundary coef for odd steps: g_coefB[t*32 + lane] = coef of slot 4*lane - 1
// (identity for lane 0). Avoids 3 shfls per odd step.
__device__ float4 g_coefB[TROWS * 32];
// W^T split into tf32 hi/lo planes: B[k=j][n=i] = Re(e^{i phe_i} U[i][j])
__device__ float g_Whi[NN * NN];
__device__ float g_Wlo[NN * NN];

__device__ __forceinline__ float tf32_rna(float x) {
    unsigned u;
    asm("cvt.rna.tf32.f32 %0, %1;" : "=r"(u) : "f"(x));
    return __uint_as_float(u);
}

// ---------------------------------------------------------------------------
// Kernel A: schedule-ordered coefficients, SoA + boundary plane.
// ---------------------------------------------------------------------------
__global__ void coef2_kernel(const float* __restrict__ theta,
                             const float* __restrict__ phi) {
    const int t = blockIdx.x;        // 0..TROWS-1
    const int m = threadIdx.x;       // 0..127 (slot)
    const int p = 2 * m + (t & 1);
    const int pmaxs = min(t, 508 - t);   // negative for t > 508
    float4 out = make_float4(1.f, 0.f, 0.f, 0.f);
    if (p <= pmaxs) {                // implies t <= 508, p <= 254, l in range
        const int l = (t - p) >> 1;
        const int idx = l * 255 - ((l * (l - 1)) >> 1) + p;
        float s, c;  sincosf(theta[idx], &s, &c);
        float ei, er; sincosf(phi[idx], &ei, &er);
        out = make_float4(c, s * er, s * ei, 0.f);
    }
    g_coef2[t * 128 + (m & 3) * 32 + (m >> 2)] = out;
    // boundary plane: slot m = 4i-1 feeds lane i's lower boundary
    if ((m & 3) == 3 && m < 127)
        g_coefB[t * 32 + ((m + 1) >> 2)] = out;
    if (m == 0)
        g_coefB[t * 32] = make_float4(1.f, 0.f, 0.f, 0.f);
}

// ---------------------------------------------------------------------------
// Kernel B: one warp per column; rows 8i..8i+7 in lane i's registers.
// (R9 configuration: 128 thr/CTA, 64 CTAs, 1 warp/SMSP — measured optimum.)
// Epilogue emits tf32 hi/lo planes of W^T for the tensor-core GEMM.
// ---------------------------------------------------------------------------
#define MZI(cf, x0, y0, x1, y1) do {                       \
    const float c_ = (cf).x, sr_ = (cf).y, si_ = (cf).z;   \
    const float nx0 = c_*(x0) - sr_*(x1) - si_*(y1);       \
    const float ny0 = c_*(y0) - sr_*(y1) + si_*(x1);       \
    const float nx1 = sr_*(x0) - si_*(y0) + c_*(x1);       \
    const float ny1 = sr_*(y0) + si_*(x0) + c_*(y1);       \
    (x0) = nx0; (y0) = ny0; (x1) = nx1; (y1) = ny1;        \
} while (0)

#define LOADP(dst, tt) do {                                            \
    const float4* p_ = &g_coef2[(tt) * 128 + lane];                    \
    dst[0] = __ldg(p_);       dst[1] = __ldg(p_ + 32);                 \
    dst[2] = __ldg(p_ + 64);  dst[3] = __ldg(p_ + 96);                 \
} while (0)

#define LOADB(bdst, tt) do {                                           \
    bdst = __ldg(&g_coefB[(tt) * 32 + lane]);                          \
} while (0)

#define STEP_EVEN(cf) do {                                             \
    MZI(cf[0], vr[0], vi[0], vr[1], vi[1]);                            \
    MZI(cf[1], vr[2], vi[2], vr[3], vi[3]);                            \
    MZI(cf[2], vr[4], vi[4], vr[5], vi[5]);                            \
    MZI(cf[3], vr[6], vi[6], vr[7], vi[7]);                            \
} while (0)

#define STEP_ODD(cf, bcf) do {                                         \
    const float rx = __shfl_down_sync(0xffffffffu, vr[0], 1);          \
    const float ry = __shfl_down_sync(0xffffffffu, vi[0], 1);          \
    const float lx = __shfl_up_sync(0xffffffffu, vr[7], 1);            \
    const float ly = __shfl_up_sync(0xffffffffu, vi[7], 1);            \
    MZI(cf[0], vr[1], vi[1], vr[2], vi[2]);                            \
    MZI(cf[1], vr[3], vi[3], vr[4], vi[4]);                            \
    MZI(cf[2], vr[5], vi[5], vr[6], vi[6]);                            \
    {   /* upper boundary: this lane's row 7 is v0 -> n0 */            \
        const float c_ = cf[3].x, sr_ = cf[3].y, si_ = cf[3].z;        \
        const float nx = c_*vr[7] - sr_*rx - si_*ry;                   \
        const float ny = c_*vi[7] - sr_*ry + si_*rx;                   \
        vr[7] = nx; vi[7] = ny;                                        \
    }                                                                  \
    {   /* lower boundary: this lane's row 0 is v1 -> n1 */            \
        const float bc = bcf.x, bs = bcf.y, bt = bcf.z;                \
        const float nx = bs*lx - bt*ly + bc*vr[0];                     \
        const float ny = bs*ly + bt*lx + bc*vi[0];                     \
        vr[0] = nx; vi[0] = ny;                                        \
    }                                                                  \
} while (0)

__global__ __launch_bounds__(128, 1) void build_u_kernel(const float* __restrict__ phi_ext) {
    const int lane = threadIdx.x & 31;
    const int j = blockIdx.x * 4 + (threadIdx.x >> 5);   // column, one per warp

    float vr[8], vi[8];
    #pragma unroll
    for (int k = 0; k < 8; ++k) {
        vr[k] = (8 * lane + k == j) ? 1.f : 0.f;
        vi[k] = 0.f;
    }

    float4 e0[4], o0[4], e1[4], o1[4], e2[4], o2[4];
    float4 b0, b1, b2;
    LOADP(e0, 0); LOADP(o0, 1); LOADB(b0, 1);
    LOADP(e1, 2); LOADP(o1, 3); LOADB(b1, 3);
    LOADP(e2, 4); LOADP(o2, 5); LOADB(b2, 5);

    int t = 6;
    #pragma unroll 1
    for (int it = 0; it < 85; ++it) {     // 85*6 = 510 steps (0..509; 509 inert)
        STEP_EVEN(e0); STEP_ODD(o0, b0);
        LOADP(e0, t); LOADP(o0, t + 1); LOADB(b0, t + 1);
        STEP_EVEN(e1); STEP_ODD(o1, b1);
        LOADP(e1, t + 2); LOADP(o1, t + 3); LOADB(b1, t + 3);
        STEP_EVEN(e2); STEP_ODD(o2, b2);
        LOADP(e2, t + 4); LOADP(o2, t + 5); LOADB(b2, t + 5);
        t += 6;
    }

    // phase screen, real part, split into tf32 hi/lo planes
    #pragma unroll
    for (int k = 0; k < 8; ++k) {
        const int r = 8 * lane + k;
        float sp, cp;
        sincosf(__ldg(&phi_ext[r]), &sp, &cp);
        const float w = cp * vr[k] - sp * vi[k];
        const float hi = tf32_rna(w);
        const float lo = tf32_rna(w - hi);
        g_Whi[j * NN + r] = hi;
        g_Wlo[j * NN + r] = lo;
    }
}

// ---------------------------------------------------------------------------
// Kernel C: out = x @ W^T via 3xTF32 tensor-core GEMM.
// C[4096,256] = A[4096,256] * B[256,256], B[k][n] = g_Whi/g_Wlo (tf32 split).
// CTA tile 128x128, 8 warps (4m x 2n), warp tile 32x64, BK=16 (2 x k8).
// D += Ah*Bh + Ah*Bl + Al*Bh  (split residual ~2^-22 — fp32-grade accuracy).
// ---------------------------------------------------------------------------
#define GBM 128
#define GBN 128
#define GBK 16
#define SPITCH 132   // padded row: float4-aligned (132*4B = 528B, 16B multiple)

__device__ __forceinline__ void mma_tf32(float* d, const unsigned* a,
                                         unsigned b0, unsigned b1) {
    asm volatile(
        "mma.sync.aligned.m16n8k8.row.col.f32.tf32.tf32.f32 "
        "{%0,%1,%2,%3}, {%4,%5,%6,%7}, {%8,%9}, {%0,%1,%2,%3};"
        : "+f"(d[0]), "+f"(d[1]), "+f"(d[2]), "+f"(d[3])
        : "r"(a[0]), "r"(a[1]), "r"(a[2]), "r"(a[3]), "r"(b0), "r"(b1));
}

__global__ __launch_bounds__(256, 1) void gemm_tc_kernel(const float* __restrict__ A,
                                                         float* __restrict__ C) {
    __shared__ float Ah[GBK][SPITCH], Al[GBK][SPITCH];
    __shared__ float Bh[GBK][SPITCH], Bl[GBK][SPITCH];

    const int tid  = threadIdx.x;
    const int wid  = tid >> 5;
    const int lane = tid & 31;
    const int g    = lane >> 2;       // 0..7
    const int th   = lane & 3;        // 0..3
    const int wm0  = (wid & 3) * 32;  // warp m offset in CTA tile
    const int wn0  = (wid >> 2) * 64; // warp n offset
    const int bm0  = blockIdx.x * GBM;
    const int bn0  = blockIdx.y * GBN;

    // A staging: thread -> (row am, k offset akc in {0,8})
    const int am  = tid >> 1;
    const int akc = (tid & 1) * 8;
    // B staging: thread -> (k row bk, n offset bnc)
    const int bk  = tid >> 4;
    const int bnc = (tid & 15) * 8;

    float acc[2][8][4];
    #pragma unroll
    for (int mt = 0; mt < 2; ++mt)
        #pragma unroll
        for (int nt = 0; nt < 8; ++nt)
            #pragma unroll
            for (int q = 0; q < 4; ++q) acc[mt][nt][q] = 0.f;

    // prefetch iter 0
    float4 pa0, pa1, pbh0, pbh1, pbl0, pbl1;
    {
        const float* ap = A + (bm0 + am) * NN + akc;
        pa0 = *reinterpret_cast<const float4*>(ap);
        pa1 = *reinterpret_cast<const float4*>(ap + 4);
        const float* bp = g_Whi + bk * NN + bn0 + bnc;
        const float* cp = g_Wlo + bk * NN + bn0 + bnc;
        pbh0 = *reinterpret_cast<const float4*>(bp);
        pbh1 = *reinterpret_cast<const float4*>(bp + 4);
        pbl0 = *reinterpret_cast<const float4*>(cp);
        pbl1 = *reinterpret_cast<const float4*>(cp + 4);
    }

    #pragma unroll 1
    for (int it = 0; it < NN / GBK; ++it) {
        // stage prefetched data (split x into tf32 hi/lo)
        {
            float av[8] = {pa0.x, pa0.y, pa0.z, pa0.w, pa1.x, pa1.y, pa1.z, pa1.w};
            #pragma unroll
            for (int u = 0; u < 8; ++u) {
                const float hi = tf32_rna(av[u]);
                Ah[akc + u][am] = hi;
                Al[akc + u][am] = tf32_rna(av[u] - hi);
            }
            *reinterpret_cast<float4*>(&Bh[bk][bnc])     = pbh0;
            *reinterpret_cast<float4*>(&Bh[bk][bnc + 4]) = pbh1;
            *reinterpret_cast<float4*>(&Bl[bk][bnc])     = pbl0;
            *reinterpret_cast<float4*>(&Bl[bk][bnc + 4]) = pbl1;
        }
        __syncthreads();

        // prefetch next iter while computing
        if (it + 1 < NN / GBK) {
            const int k0 = (it + 1) * GBK;
            const float* ap = A + (bm0 + am) * NN + k0 + akc;
            pa0 = *reinterpret_cast<const float4*>(ap);
            pa1 = *reinterpret_cast<const float4*>(ap + 4);
            const float* bp = g_Whi + (k0 + bk) * NN + bn0 + bnc;
            const float* cp = g_Wlo + (k0 + bk) * NN + bn0 + bnc;
            pbh0 = *reinterpret_cast<const float4*>(bp);
            pbh1 = *reinterpret_cast<const float4*>(bp + 4);
            pbl0 = *reinterpret_cast<const float4*>(cp);
            pbl1 = *reinterpret_cast<const float4*>(cp + 4);
        }

        #pragma unroll
        for (int ks = 0; ks < GBK; ks += 8) {
            unsigned ah[2][4], al[2][4];
            #pragma unroll
            for (int mt = 0; mt < 2; ++mt) {
                const int mb = wm0 + mt * 16 + g;
                ah[mt][0] = __float_as_uint(Ah[ks + th][mb]);
                ah[mt][1] = __float_as_uint(Ah[ks + th][mb + 8]);
                ah[mt][2] = __float_as_uint(Ah[ks + th + 4][mb]);
                ah[mt][3] = __float_as_uint(Ah[ks + th + 4][mb + 8]);
                al[mt][0] = __float_as_uint(Al[ks + th][mb]);
                al[mt][1] = __float_as_uint(Al[ks + th][mb + 8]);
                al[mt][2] = __float_as_uint(Al[ks + th + 4][mb]);
                al[mt][3] = __float_as_uint(Al[ks + th + 4][mb + 8]);
            }
            #pragma unroll
            for (int nt = 0; nt < 8; ++nt) {
                const int nb = wn0 + nt * 8 + g;
                const unsigned bh0 = __float_as_uint(Bh[ks + th][nb]);
                const unsigned bh1 = __float_as_uint(Bh[ks + th + 4][nb]);
                const unsigned bl0 = __float_as_uint(Bl[ks + th][nb]);
                const unsigned bl1 = __float_as_uint(Bl[ks + th + 4][nb]);
                #pragma unroll
                for (int mt = 0; mt < 2; ++mt) {
                    mma_tf32(acc[mt][nt], ah[mt], bh0, bh1);
                    mma_tf32(acc[mt][nt], ah[mt], bl0, bl1);
                    mma_tf32(acc[mt][nt], al[mt], bh0, bh1);
                }
            }
        }
        __syncthreads();
    }

    // epilogue: c0,c1 -> (row g, col 2th..2th+1); c2,c3 -> row g+8
    #pragma unroll
    for (int mt = 0; mt < 2; ++mt) {
        #pragma unroll
        for (int nt = 0; nt < 8; ++nt) {
            const int row = bm0 + wm0 + mt * 16 + g;
            const int col = bn0 + wn0 + nt * 8 + 2 * th;
            *reinterpret_cast<float2*>(C + row * NN + col) =
                make_float2(acc[mt][nt][0], acc[mt][nt][1]);
            *reinterpret_cast<float2*>(C + (row + 8) * NN + col) =
                make_float2(acc[mt][nt][2], acc[mt][nt][3]);
        }
    }
}

// ---------------------------------------------------------------------------
// Launch: inputs (metadata order): x, theta, phi_internal, phi_external
// ---------------------------------------------------------------------------
extern "C" void kernel_launch(void* const* d_in, const int* in_sizes, int n_in,
                              void* d_out, int out_size) {
    const float* x       = (const float*)d_in[0];
    const float* theta   = (const float*)d_in[1];
    const float* phi_int = (const float*)d_in[2];
    const float* phi_ext = (const float*)d_in[3];
    float* out = (float*)d_out;

    coef2_kernel<<<TROWS, 128>>>(theta, phi_int);
    build_u_kernel<<<NN / 4, 128>>>(phi_ext);
    gemm_tc_kernel<<<dim3(BATCH / GBM, NN / GBN), 256>>>(x, out);
}

// round 12
// speedup vs baseline: 1.2927x; 1.1220x over previous
#include <cuda_runtime.h>
#include <math.h>

#define NN 256
#define BATCH 4096
#define TROWS 520          // padded step rows (active t: 0..508)

// Scratch (no device allocations allowed)
// Full layout SoA: g_coef2[t*128 + k*32 + lane] = coef for slot m = 4*lane+k
__device__ float4 g_coef2[TROWS * 128];
// Full boundary plane: g_coefB[t*32 + lane] = coef of slot m = 4*lane-1
__device__ float4 g_coefB[TROWS * 32];
// Half layout SoA: g_coefH[t*64 + k*32 + lane] = coef for slot m = 2*lane+k
__device__ float4 g_coefH[TROWS * 64];
// Half boundary plane: g_coefHB[t*32 + lane] = coef of slot m = 2*lane-1
__device__ float4 g_coefHB[TROWS * 32];
__device__ float  g_Wt[NN * NN];   // g_Wt[j*NN + i] = Re(e^{i phe_i} U[i][j])

// ---------------------------------------------------------------------------
// Kernel A: schedule-ordered coefficients (identity for inactive slots),
// scattered into full-layout and half-layout SoA planes.
// ---------------------------------------------------------------------------
__global__ void coef2_kernel(const float* __restrict__ theta,
                             const float* __restrict__ phi) {
    const int t = blockIdx.x;        // 0..TROWS-1
    const int m = threadIdx.x;       // 0..127 (slot)
    const int p = 2 * m + (t & 1);
    const int pmaxs = min(t, 508 - t);   // negative for t > 508
    float4 out = make_float4(1.f, 0.f, 0.f, 0.f);
    if (p <= pmaxs) {
        const int l = (t - p) >> 1;
        const int idx = l * 255 - ((l * (l - 1)) >> 1) + p;
        float s, c;  sincosf(theta[idx], &s, &c);
        float ei, er; sincosf(phi[idx], &ei, &er);
        out = make_float4(c, s * er, s * ei, 0.f);
    }
    // full layout
    g_coef2[t * 128 + (m & 3) * 32 + (m >> 2)] = out;
    if ((m & 3) == 3 && m < 127)
        g_coefB[t * 32 + ((m + 1) >> 2)] = out;
    if (m == 0)
        g_coefB[t * 32] = make_float4(1.f, 0.f, 0.f, 0.f);
    // half layout (slots m < 64)
    if (m < 64)
        g_coefH[t * 64 + (m & 1) * 32 + (m >> 1)] = out;
    if ((m & 1) == 1 && m <= 61)
        g_coefHB[t * 32 + ((m + 1) >> 1)] = out;
    if (m == 0)
        g_coefHB[t * 32] = make_float4(1.f, 0.f, 0.f, 0.f);
}

// ---------------------------------------------------------------------------
// Kernel B: warp-per-column systolic build, wavefront-phased layouts.
// Phase 1 (t=0..125):   rows 0..127 only -> half layout (4 rows/lane, 24 FMA/step)
// Phase 2 (t=126..383): full layout (8 rows/lane, 48 FMA/step)  [R9-proven]
// Phase 3 (t=384..509): rows 0..127 only -> half layout
// ---------------------------------------------------------------------------
#define MZI(cf, x0, y0, x1, y1) do {                       \
    const float c_ = (cf).x, sr_ = (cf).y, si_ = (cf).z;   \
    const float nx0 = c_*(x0) - sr_*(x1) - si_*(y1);       \
    const float ny0 = c_*(y0) - sr_*(y1) + si_*(x1);       \
    const float nx1 = sr_*(x0) - si_*(y0) + c_*(x1);       \
    const float ny1 = sr_*(y0) + si_*(x0) + c_*(y1);       \
    (x0) = nx0; (y0) = ny0; (x1) = nx1; (y1) = ny1;        \
} while (0)

// ---- full layout ----
#define LOADP(dst, tt) do {                                            \
    const float4* p_ = &g_coef2[(tt) * 128 + lane];                    \
    dst[0] = __ldg(p_);       dst[1] = __ldg(p_ + 32);                 \
    dst[2] = __ldg(p_ + 64);  dst[3] = __ldg(p_ + 96);                 \
} while (0)

#define LOADB(bdst, tt) do {                                           \
    bdst = __ldg(&g_coefB[(tt) * 32 + lane]);                          \
} while (0)

#define STEP_EVEN(cf) do {                                             \
    MZI(cf[0], vr[0], vi[0], vr[1], vi[1]);                            \
    MZI(cf[1], vr[2], vi[2], vr[3], vi[3]);                            \
    MZI(cf[2], vr[4], vi[4], vr[5], vi[5]);                            \
    MZI(cf[3], vr[6], vi[6], vr[7], vi[7]);                            \
} while (0)

#define STEP_ODD(cf, bcf) do {                                         \
    const float rx = __shfl_down_sync(0xffffffffu, vr[0], 1);          \
    const float ry = __shfl_down_sync(0xffffffffu, vi[0], 1);          \
    const float lx = __shfl_up_sync(0xffffffffu, vr[7], 1);            \
    const float ly = __shfl_up_sync(0xffffffffu, vi[7], 1);            \
    MZI(cf[0], vr[1], vi[1], vr[2], vi[2]);                            \
    MZI(cf[1], vr[3], vi[3], vr[4], vi[4]);                            \
    MZI(cf[2], vr[5], vi[5], vr[6], vi[6]);                            \
    {                                                                  \
        const float c_ = cf[3].x, sr_ = cf[3].y, si_ = cf[3].z;        \
        const float nx = c_*vr[7] - sr_*rx - si_*ry;                   \
        const float ny = c_*vi[7] - sr_*ry + si_*rx;                   \
        vr[7] = nx; vi[7] = ny;                                        \
    }                                                                  \
    {                                                                  \
        const float bc = bcf.x, bs = bcf.y, bt = bcf.z;                \
        const float nx = bs*lx - bt*ly + bc*vr[0];                     \
        const float ny = bs*ly + bt*lx + bc*vi[0];                     \
        vr[0] = nx; vi[0] = ny;                                        \
    }                                                                  \
} while (0)

// ---- half layout (rows 4L..4L+3 in vr/vi[0..3]) ----
#define LOADH(dst, tt) do {                                            \
    const float4* p_ = &g_coefH[(tt) * 64 + lane];                     \
    dst[0] = __ldg(p_); dst[1] = __ldg(p_ + 32);                       \
} while (0)

#define LOADHB(bdst, tt) do {                                          \
    bdst = __ldg(&g_coefHB[(tt) * 32 + lane]);                         \
} while (0)

#define HSTEP_EVEN(cf) do {                                            \
    MZI(cf[0], vr[0], vi[0], vr[1], vi[1]);                            \
    MZI(cf[1], vr[2], vi[2], vr[3], vi[3]);                            \
} while (0)

#define HSTEP_ODD(cf, bcf) do {                                        \
    const float rx = __shfl_down_sync(0xffffffffu, vr[0], 1);          \
    const float ry = __shfl_down_sync(0xffffffffu, vi[0], 1);          \
    const float lx = __shfl_up_sync(0xffffffffu, vr[3], 1);            \
    const float ly = __shfl_up_sync(0xffffffffu, vi[3], 1);            \
    MZI(cf[0], vr[1], vi[1], vr[2], vi[2]);                            \
    {                                                                  \
        const float c_ = cf[1].x, sr_ = cf[1].y, si_ = cf[1].z;        \
        const float nx = c_*vr[3] - sr_*rx - si_*ry;                   \
        const float ny = c_*vi[3] - sr_*ry + si_*rx;                   \
        vr[3] = nx; vi[3] = ny;                                        \
    }                                                                  \
    {                                                                  \
        const float bc = bcf.x, bs = bcf.y, bt = bcf.z;                \
        const float nx = bs*lx - bt*ly + bc*vr[0];                     \
        const float ny = bs*ly + bt*lx + bc*vi[0];                     \
        vr[0] = nx; vi[0] = ny;                                        \
    }                                                                  \
} while (0)

__global__ __launch_bounds__(128, 1) void build_u_kernel(const float* __restrict__ phi_ext) {
    const int lane = threadIdx.x & 31;
    const int j = blockIdx.x * 4 + (threadIdx.x >> 5);   // column, one per warp

    float vr[8], vi[8];

    // ---------------- phase 1: half layout, t = 0..125 ----------------
    #pragma unroll
    for (int k = 0; k < 4; ++k) {
        vr[k] = (4 * lane + k == j) ? 1.f : 0.f;   // j>=128: all-zero state (correct)
        vi[k] = 0.f;
    }
    {
        float4 e0[2], o0[2], e1[2], o1[2], e2[2], o2[2];
        float4 b0, b1, b2;
        LOADH(e0, 0); LOADH(o0, 1); LOADHB(b0, 1);
        LOADH(e1, 2); LOADH(o1, 3); LOADHB(b1, 3);
        LOADH(e2, 4); LOADH(o2, 5); LOADHB(b2, 5);
        int t = 6;
        #pragma unroll 1
        for (int it = 0; it < 21; ++it) {     // steps 0..125
            HSTEP_EVEN(e0); HSTEP_ODD(o0, b0);
            LOADH(e0, t); LOADH(o0, t + 1); LOADHB(b0, t + 1);
            HSTEP_EVEN(e1); HSTEP_ODD(o1, b1);
            LOADH(e1, t + 2); LOADH(o1, t + 3); LOADHB(b1, t + 3);
            HSTEP_EVEN(e2); HSTEP_ODD(o2, b2);
            LOADH(e2, t + 4); LOADH(o2, t + 5); LOADHB(b2, t + 5);
            t += 6;
        }
    }

    // -------- transition half -> full: lane L gets rows 8L..8L+7 --------
    {
        float nr[8], ni[8];
        #pragma unroll
        for (int k = 0; k < 4; ++k) {
            const float ra = __shfl_sync(0xffffffffu, vr[k], 2 * lane);
            const float rb = __shfl_sync(0xffffffffu, vr[k], 2 * lane + 1);
            const float ia = __shfl_sync(0xffffffffu, vi[k], 2 * lane);
            const float ib = __shfl_sync(0xffffffffu, vi[k], 2 * lane + 1);
            if (lane < 16) {
                nr[k] = ra;     ni[k] = ia;
                nr[k + 4] = rb; ni[k + 4] = ib;
            } else {           // rows 128..255: still at initial e_j values
                nr[k]     = (8 * lane + k == j)     ? 1.f : 0.f; ni[k] = 0.f;
                nr[k + 4] = (8 * lane + k + 4 == j) ? 1.f : 0.f; ni[k + 4] = 0.f;
            }
        }
        #pragma unroll
        for (int k = 0; k < 8; ++k) { vr[k] = nr[k]; vi[k] = ni[k]; }
    }

    // ---------------- phase 2: full layout, t = 126..383 ----------------
    {
        float4 e0[4], o0[4], e1[4], o1[4], e2[4], o2[4];
        float4 b0, b1, b2;
        LOADP(e0, 126); LOADP(o0, 127); LOADB(b0, 127);
        LOADP(e1, 128); LOADP(o1, 129); LOADB(b1, 129);
        LOADP(e2, 130); LOADP(o2, 131); LOADB(b2, 131);
        int t = 132;
        #pragma unroll 1
        for (int it = 0; it < 43; ++it) {     // steps 126..383
            STEP_EVEN(e0); STEP_ODD(o0, b0);
            LOADP(e0, t); LOADP(o0, t + 1); LOADB(b0, t + 1);
            STEP_EVEN(e1); STEP_ODD(o1, b1);
            LOADP(e1, t + 2); LOADP(o1, t + 3); LOADB(b1, t + 3);
            STEP_EVEN(e2); STEP_ODD(o2, b2);
            LOADP(e2, t + 4); LOADP(o2, t + 5); LOADB(b2, t + 5);
            t += 6;
        }
    }

    // -------- transition full -> half: rows 128..255 final, store now --------
    if (lane >= 16) {
        #pragma unroll
        for (int k = 0; k < 8; ++k) {
            const int r = 8 * lane + k;     // 128..255
            float sp, cp;
            sincosf(__ldg(&phi_ext[r]), &sp, &cp);
            g_Wt[j * NN + r] = cp * vr[k] - sp * vi[k];
        }
    }
    {   // redistribute rows 0..127: lane L gets rows 4L..4L+3
        float nr[4], ni[4];
        #pragma unroll
        for (int k = 0; k < 4; ++k) {
            const float ra = __shfl_sync(0xffffffffu, vr[k],     lane >> 1);
            const float rb = __shfl_sync(0xffffffffu, vr[k + 4], lane >> 1);
            const float ia = __shfl_sync(0xffffffffu, vi[k],     lane >> 1);
            const float ib = __shfl_sync(0xffffffffu, vi[k + 4], lane >> 1);
            nr[k] = (lane & 1) ? rb : ra;
            ni[k] = (lane & 1) ? ib : ia;
        }
        #pragma unroll
        for (int k = 0; k < 4; ++k) { vr[k] = nr[k]; vi[k] = ni[k]; }
    }

    // ---------------- phase 3: half layout, t = 384..509 ----------------
    {
        float4 e0[2], o0[2], e1[2], o1[2], e2[2], o2[2];
        float4 b0, b1, b2;
        LOADH(e0, 384); LOADH(o0, 385); LOADHB(b0, 385);
        LOADH(e1, 386); LOADH(o1, 387); LOADHB(b1, 387);
        LOADH(e2, 388); LOADH(o2, 389); LOADHB(b2, 389);
        int t = 390;
        #pragma unroll 1
        for (int it = 0; it < 21; ++it) {     // steps 384..509 (509 inert)
            HSTEP_EVEN(e0); HSTEP_ODD(o0, b0);
            LOADH(e0, t); LOADH(o0, t + 1); LOADHB(b0, t + 1);
            HSTEP_EVEN(e1); HSTEP_ODD(o1, b1);
            LOADH(e1, t + 2); LOADH(o1, t + 3); LOADHB(b1, t + 3);
            HSTEP_EVEN(e2); HSTEP_ODD(o2, b2);
            LOADH(e2, t + 4); LOADH(o2, t + 5); LOADHB(b2, t + 5);
            t += 6;
        }
    }

    // final store: rows 0..127
    #pragma unroll
    for (int k = 0; k < 4; ++k) {
        const int r = 4 * lane + k;
        float sp, cp;
        sincosf(__ldg(&phi_ext[r]), &sp, &cp);
        g_Wt[j * NN + r] = cp * vr[k] - sp * vi[k];
    }
}

// ---------------------------------------------------------------------------
// Kernel C: out[b,i] = sum_j x[b,j] * Wt[j,i]   (84us-proven SIMT GEMM)
// BM=BN=64, BK=16, 256 threads, 4x4 per thread, float4 smem paths (pad +4).
// ---------------------------------------------------------------------------
#define BM 64
#define BN 64
#define BK 16

__global__ __launch_bounds__(256, 4) void gemm_kernel(const float* __restrict__ A,
                                                      float* __restrict__ C) {
    __shared__ float As[BK][BM + 4];
    __shared__ float Ws[BK][BN + 4];

    const int tid = threadIdx.x;
    const int tx = tid & 15;
    const int ty = tid >> 4;
    const int bm0 = blockIdx.x * BM;
    const int bn0 = blockIdx.y * BN;

    const int lr = tid >> 2;
    const int lc = (tid & 3) * 4;
    const int wr = tid >> 4;
    const int wc = (tid & 15) * 4;

    float acc[4][4] = {};

    for (int k0 = 0; k0 < NN; k0 += BK) {
        const float4 a4 = *reinterpret_cast<const float4*>(A + (bm0 + lr) * NN + k0 + lc);
        As[lc + 0][lr] = a4.x; As[lc + 1][lr] = a4.y;
        As[lc + 2][lr] = a4.z; As[lc + 3][lr] = a4.w;
        const float4 w4 = *reinterpret_cast<const float4*>(g_Wt + (k0 + wr) * NN + bn0 + wc);
        *reinterpret_cast<float4*>(&Ws[wr][wc]) = w4;
        __syncthreads();

        #pragma unroll
        for (int k = 0; k < BK; ++k) {
            const float4 am = *reinterpret_cast<const float4*>(&As[k][ty * 4]);
            const float4 bn = *reinterpret_cast<const float4*>(&Ws[k][tx * 4]);
            const float a[4] = {am.x, am.y, am.z, am.w};
            const float b[4] = {bn.x, bn.y, bn.z, bn.w};
            #pragma unroll
            for (int i = 0; i < 4; ++i)
                #pragma unroll
                for (int jj = 0; jj < 4; ++jj)
                    acc[i][jj] = fmaf(a[i], b[jj], acc[i][jj]);
        }
        __syncthreads();
    }

    #pragma unroll
    for (int i = 0; i < 4; ++i) {
        float4 r = make_float4(acc[i][0], acc[i][1], acc[i][2], acc[i][3]);
        *reinterpret_cast<float4*>(C + (bm0 + ty * 4 + i) * NN + bn0 + tx * 4) = r;
    }
}

// ---------------------------------------------------------------------------
// Launch: inputs (metadata order): x, theta, phi_internal, phi_external
// ---------------------------------------------------------------------------
extern "C" void kernel_launch(void* const* d_in, const int* in_sizes, int n_in,
                              void* d_out, int out_size) {
    const float* x       = (const float*)d_in[0];
    const float* theta   = (const float*)d_in[1];
    const float* phi_int = (const float*)d_in[2];
    const float* phi_ext = (const float*)d_in[3];
    float* out = (float*)d_out;

    coef2_kernel<<<TROWS, 128>>>(theta, phi_int);
    build_u_kernel<<<NN / 4, 128>>>(phi_ext);
    gemm_kernel<<<dim3(BATCH / BM, NN / BN), 256>>>(x, out);
}

// round 13
// speedup vs baseline: 1.3250x; 1.0250x over previous
#include <cuda_runtime.h>
#include <math.h>

#define NN 256
#define BATCH 4096
#define TROWS 520          // padded step rows (active t: 0..508)

// Scratch (no device allocations allowed)
__device__ float4 g_coef2[TROWS * 128];   // full layout SoA
__device__ float4 g_coefB[TROWS * 32];    // full boundary plane
__device__ float4 g_coefH[TROWS * 64];    // half layout SoA
__device__ float4 g_coefHB[TROWS * 32];   // half boundary plane
// W^T split into tf32 hi/lo planes: B[k=j][n=i] = Re(e^{i phe_i} U[i][j])
__device__ float g_Whi[NN * NN];
__device__ float g_Wlo[NN * NN];

__device__ __forceinline__ float tf32_rna(float x) {
    unsigned u;
    asm("cvt.rna.tf32.f32 %0, %1;" : "=r"(u) : "f"(x));
    return __uint_as_float(u);
}

// ---------------------------------------------------------------------------
// Kernel A: schedule-ordered coefficients (identity padding), 256-thr blocks.
// ---------------------------------------------------------------------------
__global__ void coef2_kernel(const float* __restrict__ theta,
                             const float* __restrict__ phi) {
    const int tid = threadIdx.x;
    const int t = blockIdx.x * 2 + (tid >> 7);   // 0..519
    const int m = tid & 127;                     // slot
    const int p = 2 * m + (t & 1);
    const int pmaxs = min(t, 508 - t);
    float4 out = make_float4(1.f, 0.f, 0.f, 0.f);
    if (p <= pmaxs) {
        const int l = (t - p) >> 1;
        const int idx = l * 255 - ((l * (l - 1)) >> 1) + p;
        float s, c;  sincosf(theta[idx], &s, &c);
        float ei, er; sincosf(phi[idx], &ei, &er);
        out = make_float4(c, s * er, s * ei, 0.f);
    }
    g_coef2[t * 128 + (m & 3) * 32 + (m >> 2)] = out;
    if ((m & 3) == 3 && m < 127)
        g_coefB[t * 32 + ((m + 1) >> 2)] = out;
    if (m == 0)
        g_coefB[t * 32] = make_float4(1.f, 0.f, 0.f, 0.f);
    if (m < 64)
        g_coefH[t * 64 + (m & 1) * 32 + (m >> 1)] = out;
    if ((m & 1) == 1 && m <= 61)
        g_coefHB[t * 32 + ((m + 1) >> 1)] = out;
    if (m == 0)
        g_coefHB[t * 32] = make_float4(1.f, 0.f, 0.f, 0.f);
}

// ---------------------------------------------------------------------------
// Kernel B: warp-per-column systolic build, wavefront-phased layouts (R12).
// Epilogues emit tf32 hi/lo planes of W^T.
// ---------------------------------------------------------------------------
#define MZI(cf, x0, y0, x1, y1) do {                       \
    const float c_ = (cf).x, sr_ = (cf).y, si_ = (cf).z;   \
    const float nx0 = c_*(x0) - sr_*(x1) - si_*(y1);       \
    const float ny0 = c_*(y0) - sr_*(y1) + si_*(x1);       \
    const float nx1 = sr_*(x0) - si_*(y0) + c_*(x1);       \
    const float ny1 = sr_*(y0) + si_*(x0) + c_*(y1);       \
    (x0) = nx0; (y0) = ny0; (x1) = nx1; (y1) = ny1;        \
} while (0)

#define LOADP(dst, tt) do {                                            \
    const float4* p_ = &g_coef2[(tt) * 128 + lane];                    \
    dst[0] = __ldg(p_);       dst[1] = __ldg(p_ + 32);                 \
    dst[2] = __ldg(p_ + 64);  dst[3] = __ldg(p_ + 96);                 \
} while (0)
#define LOADB(bdst, tt)  do { bdst = __ldg(&g_coefB[(tt) * 32 + lane]); } while (0)
#define LOADH(dst, tt) do {                                            \
    const float4* p_ = &g_coefH[(tt) * 64 + lane];                     \
    dst[0] = __ldg(p_); dst[1] = __ldg(p_ + 32);                       \
} while (0)
#define LOADHB(bdst, tt) do { bdst = __ldg(&g_coefHB[(tt) * 32 + lane]); } while (0)

#define STEP_EVEN(cf) do {                                             \
    MZI(cf[0], vr[0], vi[0], vr[1], vi[1]);                            \
    MZI(cf[1], vr[2], vi[2], vr[3], vi[3]);                            \
    MZI(cf[2], vr[4], vi[4], vr[5], vi[5]);                            \
    MZI(cf[3], vr[6], vi[6], vr[7], vi[7]);                            \
} while (0)

#define STEP_ODD(cf, bcf) do {                                         \
    const float rx = __shfl_down_sync(0xffffffffu, vr[0], 1);          \
    const float ry = __shfl_down_sync(0xffffffffu, vi[0], 1);          \
    const float lx = __shfl_up_sync(0xffffffffu, vr[7], 1);            \
    const float ly = __shfl_up_sync(0xffffffffu, vi[7], 1);            \
    MZI(cf[0], vr[1], vi[1], vr[2], vi[2]);                            \
    MZI(cf[1], vr[3], vi[3], vr[4], vi[4]);                            \
    MZI(cf[2], vr[5], vi[5], vr[6], vi[6]);                            \
    {                                                                  \
        const float c_ = cf[3].x, sr_ = cf[3].y, si_ = cf[3].z;        \
        const float nx = c_*vr[7] - sr_*rx - si_*ry;                   \
        const float ny = c_*vi[7] - sr_*ry + si_*rx;                   \
        vr[7] = nx; vi[7] = ny;                                        \
    }                                                                  \
    {                                                                  \
        const float bc = bcf.x, bs = bcf.y, bt = bcf.z;                \
        const float nx = bs*lx - bt*ly + bc*vr[0];                     \
        const float ny = bs*ly + bt*lx + bc*vi[0];                     \
        vr[0] = nx; vi[0] = ny;                                        \
    }                                                                  \
} while (0)

#define HSTEP_EVEN(cf) do {                                            \
    MZI(cf[0], vr[0], vi[0], vr[1], vi[1]);                            \
    MZI(cf[1], vr[2], vi[2], vr[3], vi[3]);                            \
} while (0)

#define HSTEP_ODD(cf, bcf) do {                                        \
    const float rx = __shfl_down_sync(0xffffffffu, vr[0], 1);          \
    const float ry = __shfl_down_sync(0xffffffffu, vi[0], 1);          \
    const float lx = __shfl_up_sync(0xffffffffu, vr[3], 1);            \
    const float ly = __shfl_up_sync(0xffffffffu, vi[3], 1);            \
    MZI(cf[0], vr[1], vi[1], vr[2], vi[2]);                            \
    {                                                                  \
        const float c_ = cf[1].x, sr_ = cf[1].y, si_ = cf[1].z;        \
        const float nx = c_*vr[3] - sr_*rx - si_*ry;                   \
        const float ny = c_*vi[3] - sr_*ry + si_*rx;                   \
        vr[3] = nx; vi[3] = ny;                                        \
    }                                                                  \
    {                                                                  \
        const float bc = bcf.x, bs = bcf.y, bt = bcf.z;                \
        const float nx = bs*lx - bt*ly + bc*vr[0];                     \
        const float ny = bs*ly + bt*lx + bc*vi[0];                     \
        vr[0] = nx; vi[0] = ny;                                        \
    }                                                                  \
} while (0)

__global__ __launch_bounds__(128, 1) void build_u_kernel(const float* __restrict__ phi_ext) {
    const int lane = threadIdx.x & 31;
    const int j = blockIdx.x * 4 + (threadIdx.x >> 5);

    float vr[8], vi[8];

    // phase 1: half layout, t = 0..125
    #pragma unroll
    for (int k = 0; k < 4; ++k) {
        vr[k] = (4 * lane + k == j) ? 1.f : 0.f;
        vi[k] = 0.f;
    }
    {
        float4 e0[2], o0[2], e1[2], o1[2], e2[2], o2[2];
        float4 b0, b1, b2;
        LOADH(e0, 0); LOADH(o0, 1); LOADHB(b0, 1);
        LOADH(e1, 2); LOADH(o1, 3); LOADHB(b1, 3);
        LOADH(e2, 4); LOADH(o2, 5); LOADHB(b2, 5);
        int t = 6;
        #pragma unroll 1
        for (int it = 0; it < 21; ++it) {
            HSTEP_EVEN(e0); HSTEP_ODD(o0, b0);
            LOADH(e0, t); LOADH(o0, t + 1); LOADHB(b0, t + 1);
            HSTEP_EVEN(e1); HSTEP_ODD(o1, b1);
            LOADH(e1, t + 2); LOADH(o1, t + 3); LOADHB(b1, t + 3);
            HSTEP_EVEN(e2); HSTEP_ODD(o2, b2);
            LOADH(e2, t + 4); LOADH(o2, t + 5); LOADHB(b2, t + 5);
            t += 6;
        }
    }

    // transition half -> full
    {
        float nr[8], ni[8];
        #pragma unroll
        for (int k = 0; k < 4; ++k) {
            const float ra = __shfl_sync(0xffffffffu, vr[k], 2 * lane);
            const float rb = __shfl_sync(0xffffffffu, vr[k], 2 * lane + 1);
            const float ia = __shfl_sync(0xffffffffu, vi[k], 2 * lane);
            const float ib = __shfl_sync(0xffffffffu, vi[k], 2 * lane + 1);
            if (lane < 16) {
                nr[k] = ra;     ni[k] = ia;
                nr[k + 4] = rb; ni[k + 4] = ib;
            } else {
                nr[k]     = (8 * lane + k == j)     ? 1.f : 0.f; ni[k] = 0.f;
                nr[k + 4] = (8 * lane + k + 4 == j) ? 1.f : 0.f; ni[k + 4] = 0.f;
            }
        }
        #pragma unroll
        for (int k = 0; k < 8; ++k) { vr[k] = nr[k]; vi[k] = ni[k]; }
    }

    // phase 2: full layout, t = 126..383
    {
        float4 e0[4], o0[4], e1[4], o1[4], e2[4], o2[4];
        float4 b0, b1, b2;
        LOADP(e0, 126); LOADP(o0, 127); LOADB(b0, 127);
        LOADP(e1, 128); LOADP(o1, 129); LOADB(b1, 129);
        LOADP(e2, 130); LOADP(o2, 131); LOADB(b2, 131);
        int t = 132;
        #pragma unroll 1
        for (int it = 0; it < 43; ++it) {
            STEP_EVEN(e0); STEP_ODD(o0, b0);
            LOADP(e0, t); LOADP(o0, t + 1); LOADB(b0, t + 1);
            STEP_EVEN(e1); STEP_ODD(o1, b1);
            LOADP(e1, t + 2); LOADP(o1, t + 3); LOADB(b1, t + 3);
            STEP_EVEN(e2); STEP_ODD(o2, b2);
            LOADP(e2, t + 4); LOADP(o2, t + 5); LOADB(b2, t + 5);
            t += 6;
        }
    }

    // transition full -> half: rows 128..255 are final -> store hi/lo planes
    if (lane >= 16) {
        #pragma unroll
        for (int k = 0; k < 8; ++k) {
            const int r = 8 * lane + k;
            float sp, cp;
            sincosf(__ldg(&phi_ext[r]), &sp, &cp);
            const float w = cp * vr[k] - sp * vi[k];
            const float hi = tf32_rna(w);
            g_Whi[j * NN + r] = hi;
            g_Wlo[j * NN + r] = tf32_rna(w - hi);
        }
    }
    {
        float nr[4], ni[4];
        #pragma unroll
        for (int k = 0; k < 4; ++k) {
            const float ra = __shfl_sync(0xffffffffu, vr[k],     lane >> 1);
            const float rb = __shfl_sync(0xffffffffu, vr[k + 4], lane >> 1);
            const float ia = __shfl_sync(0xffffffffu, vi[k],     lane >> 1);
            const float ib = __shfl_sync(0xffffffffu, vi[k + 4], lane >> 1);
            nr[k] = (lane & 1) ? rb : ra;
            ni[k] = (lane & 1) ? ib : ia;
        }
        #pragma unroll
        for (int k = 0; k < 4; ++k) { vr[k] = nr[k]; vi[k] = ni[k]; }
    }

    // phase 3: half layout, t = 384..509
    {
        float4 e0[2], o0[2], e1[2], o1[2], e2[2], o2[2];
        float4 b0, b1, b2;
        LOADH(e0, 384); LOADH(o0, 385); LOADHB(b0, 385);
        LOADH(e1, 386); LOADH(o1, 387); LOADHB(b1, 387);
        LOADH(e2, 388); LOADH(o2, 389); LOADHB(b2, 389);
        int t = 390;
        #pragma unroll 1
        for (int it = 0; it < 21; ++it) {
            HSTEP_EVEN(e0); HSTEP_ODD(o0, b0);
            LOADH(e0, t); LOADH(o0, t + 1); LOADHB(b0, t + 1);
            HSTEP_EVEN(e1); HSTEP_ODD(o1, b1);
            LOADH(e1, t + 2); LOADH(o1, t + 3); LOADHB(b1, t + 3);
            HSTEP_EVEN(e2); HSTEP_ODD(o2, b2);
            LOADH(e2, t + 4); LOADH(o2, t + 5); LOADHB(b2, t + 5);
            t += 6;
        }
    }

    // final store: rows 0..127 -> hi/lo planes
    #pragma unroll
    for (int k = 0; k < 4; ++k) {
        const int r = 4 * lane + k;
        float sp, cp;
        sincosf(__ldg(&phi_ext[r]), &sp, &cp);
        const float w = cp * vr[k] - sp * vi[k];
        const float hi = tf32_rna(w);
        g_Whi[j * NN + r] = hi;
        g_Wlo[j * NN + r] = tf32_rna(w - hi);
    }
}

// ---------------------------------------------------------------------------
// Kernel C: 3xTF32 tensor-core GEMM, occupancy-tuned.
// CTA tile 64x64, 128 thr (4 warps, each 32x32), grid 64x4 = 256 CTAs.
// SPITCH=72 -> fragment LDS hits 32 distinct banks (conflict-free).
// D += Ah*Bh + Ah*Bl + Al*Bh.
// ---------------------------------------------------------------------------
#define GBM 64
#define GBN 64
#define GBK 16
#define SP  72

__device__ __forceinline__ void mma_tf32(float* d, const unsigned* a,
                                         unsigned b0, unsigned b1) {
    asm volatile(
        "mma.sync.aligned.m16n8k8.row.col.f32.tf32.tf32.f32 "
        "{%0,%1,%2,%3}, {%4,%5,%6,%7}, {%8,%9}, {%0,%1,%2,%3};"
        : "+f"(d[0]), "+f"(d[1]), "+f"(d[2]), "+f"(d[3])
        : "r"(a[0]), "r"(a[1]), "r"(a[2]), "r"(a[3]), "r"(b0), "r"(b1));
}

__global__ __launch_bounds__(128, 4) void gemm_tc_kernel(const float* __restrict__ A,
                                                         float* __restrict__ C) {
    __shared__ float Ah[GBK][SP], Al[GBK][SP], Bh[GBK][SP], Bl[GBK][SP];

    const int tid  = threadIdx.x;
    const int wid  = tid >> 5;
    const int lane = tid & 31;
    const int g    = lane >> 2;
    const int th   = lane & 3;
    const int wm0  = (wid & 1) * 32;
    const int wn0  = (wid >> 1) * 32;
    const int bm0  = blockIdx.x * GBM;
    const int bn0  = blockIdx.y * GBN;

    const int am  = tid >> 1;          // 0..63
    const int akc = (tid & 1) * 8;     // 0 or 8
    const int bk  = tid >> 3;          // 0..15
    const int bnc = (tid & 7) * 8;     // 0..56

    float acc[2][4][4];
    #pragma unroll
    for (int mt = 0; mt < 2; ++mt)
        #pragma unroll
        for (int nt = 0; nt < 4; ++nt)
            #pragma unroll
            for (int q = 0; q < 4; ++q) acc[mt][nt][q] = 0.f;

    float4 pa0, pa1, pbh0, pbh1, pbl0, pbl1;
    {
        const float* ap = A + (bm0 + am) * NN + akc;
        pa0 = *reinterpret_cast<const float4*>(ap);
        pa1 = *reinterpret_cast<const float4*>(ap + 4);
        const float* bp = g_Whi + bk * NN + bn0 + bnc;
        const float* cp2 = g_Wlo + bk * NN + bn0 + bnc;
        pbh0 = *reinterpret_cast<const float4*>(bp);
        pbh1 = *reinterpret_cast<const float4*>(bp + 4);
        pbl0 = *reinterpret_cast<const float4*>(cp2);
        pbl1 = *reinterpret_cast<const float4*>(cp2 + 4);
    }

    #pragma unroll 1
    for (int it = 0; it < NN / GBK; ++it) {
        {
            float av[8] = {pa0.x, pa0.y, pa0.z, pa0.w, pa1.x, pa1.y, pa1.z, pa1.w};
            #pragma unroll
            for (int u = 0; u < 8; ++u) {
                const float hi = tf32_rna(av[u]);
                Ah[akc + u][am] = hi;
                Al[akc + u][am] = tf32_rna(av[u] - hi);
            }
            *reinterpret_cast<float4*>(&Bh[bk][bnc])     = pbh0;
            *reinterpret_cast<float4*>(&Bh[bk][bnc + 4]) = pbh1;
            *reinterpret_cast<float4*>(&Bl[bk][bnc])     = pbl0;
            *reinterpret_cast<float4*>(&Bl[bk][bnc + 4]) = pbl1;
        }
        __syncthreads();

        if (it + 1 < NN / GBK) {
            const int k0 = (it + 1) * GBK;
            const float* ap = A + (bm0 + am) * NN + k0 + akc;
            pa0 = *reinterpret_cast<const float4*>(ap);
            pa1 = *reinterpret_cast<const float4*>(ap + 4);
            const float* bp = g_Whi + (k0 + bk) * NN + bn0 + bnc;
            const float* cp2 = g_Wlo + (k0 + bk) * NN + bn0 + bnc;
            pbh0 = *reinterpret_cast<const float4*>(bp);
            pbh1 = *reinterpret_cast<const float4*>(bp + 4);
            pbl0 = *reinterpret_cast<const float4*>(cp2);
            pbl1 = *reinterpret_cast<const float4*>(cp2 + 4);
        }

        #pragma unroll
        for (int ks = 0; ks < GBK; ks += 8) {
            unsigned ah[2][4], al[2][4];
            #pragma unroll
            for (int mt = 0; mt < 2; ++mt) {
                const int mb = wm0 + mt * 16 + g;
                ah[mt][0] = __float_as_uint(Ah[ks + th][mb]);
                ah[mt][1] = __float_as_uint(Ah[ks + th][mb + 8]);
                ah[mt][2] = __float_as_uint(Ah[ks + th + 4][mb]);
                ah[mt][3] = __float_as_uint(Ah[ks + th + 4][mb + 8]);
                al[mt][0] = __float_as_uint(Al[ks + th][mb]);
                al[mt][1] = __float_as_uint(Al[ks + th][mb + 8]);
                al[mt][2] = __float_as_uint(Al[ks + th + 4][mb]);
                al[mt][3] = __float_as_uint(Al[ks + th + 4][mb + 8]);
            }
            #pragma unroll
            for (int nt = 0; nt < 4; ++nt) {
                const int nb = wn0 + nt * 8 + g;
                const unsigned bh0 = __float_as_uint(Bh[ks + th][nb]);
                const unsigned bh1 = __float_as_uint(Bh[ks + th + 4][nb]);
                const unsigned bl0 = __float_as_uint(Bl[ks + th][nb]);
                const unsigned bl1 = __float_as_uint(Bl[ks + th + 4][nb]);
                #pragma unroll
                for (int mt = 0; mt < 2; ++mt) {
                    mma_tf32(acc[mt][nt], ah[mt], bh0, bh1);
                    mma_tf32(acc[mt][nt], ah[mt], bl0, bl1);
                    mma_tf32(acc[mt][nt], al[mt], bh0, bh1);
                }
            }
        }
        __syncthreads();
    }

    #pragma unroll
    for (int mt = 0; mt < 2; ++mt) {
        #pragma unroll
        for (int nt = 0; nt < 4; ++nt) {
            const int row = bm0 + wm0 + mt * 16 + g;
            const int col = bn0 + wn0 + nt * 8 + 2 * th;
            *reinterpret_cast<float2*>(C + row * NN + col) =
                make_float2(acc[mt][nt][0], acc[mt][nt][1]);
            *reinterpret_cast<float2*>(C + (row + 8) * NN + col) =
                make_float2(acc[mt][nt][2], acc[mt][nt][3]);
        }
    }
}

// ---------------------------------------------------------------------------
// Launch: inputs (metadata order): x, theta, phi_internal, phi_external
// ---------------------------------------------------------------------------
extern "C" void kernel_launch(void* const* d_in, const int* in_sizes, int n_in,
                              void* d_out, int out_size) {
    const float* x       = (const float*)d_in[0];
    const float* theta   = (const float*)d_in[1];
    const float* phi_int = (const float*)d_in[2];
    const float* phi_ext = (const float*)d_in[3];
    float* out = (float*)d_out;

    coef2_kernel<<<TROWS / 2, 256>>>(theta, phi_int);
    build_u_kernel<<<NN / 4, 128>>>(phi_ext);
    gemm_tc_kernel<<<dim3(BATCH / GBM, NN / GBN), 128>>>(x, out);
}